// round 14
// baseline (speedup 1.0000x reference)
#include <cuda_runtime.h>

#define CH 6
#define MODES 16
#define BB 32
#define NPT 65536
#define NMASK 65535
#define TSTEPS 8

#define EXT 1026                 // logical window: indices 0..1025
#define SROW 1032                // padded row stride (float4 alignment)
#define VMARG 29                 // validity margin after 28 stage-shrinks (+1 end)
#define CORE 968                 // EXT - 2*VMARG, valid output core [29, 997)
#define NBLK 68                  // 68*968 = 65824 >= NPT
#define RKTHREADS 256            // 4 points/thread tile [1,1025) exactly
#define EDG 260                  // per-channel stride in edge arrays
#define FBLK 8                   // blocks per (b,i) in forward DFT
#define SSEG 16                  // synth segments per batch (512 blocks)

// -------- scratch (no allocations allowed) --------
__device__ float g_bufA[BB*CH*NPT];
__device__ float g_part[BB*CH*FBLK*MODES*2];

__device__ __forceinline__ float htanh(float x){
    float y;
    asm("tanh.approx.f32 %0, %1;" : "=f"(y) : "f"(x));
    return y;
}

// ---------------- stage ----------------
// 4 points/thread: own p0+1..p0+4 (p0=4*tid), window [p0, p0+5]; threads tile
// [1,1025) exactly — NO tail. Linearity split: cu = conv(u)+bias (stage 0);
// stages 1-3: a = cu + cc*conv(k). Weights/bias in SMEM (broadcast LDS).
// Edge arrays (double-buffered, stride-1): eL[i]=k(4i) (i=0 sentinel),
// eR[i]=k(4i+1) (i=256 sentinel). Stages 1-3 read ONLY edges/kr (not su).

template<int S>
__device__ __forceinline__ void stage(
    float (&cu)[CH][4],
    const float* __restrict__ eLr, const float* __restrict__ eRr,
    float* __restrict__ eLw, float* __restrict__ eRw,
    const float* __restrict__ su,
    const float* __restrict__ sw, const float* __restrict__ sb,
    float cc, float aw, int gofs, int tid, bool edge,
    float (&kr)[CH][4], float (&acc)[CH][4])
{
    const int p0 = 4*tid;
    float a[CH][4];
    #pragma unroll
    for (int co=0; co<CH; co++){ a[co][0]=0.f; a[co][1]=0.f; a[co][2]=0.f; a[co][3]=0.f; }

    if (S == 0){
        #pragma unroll
        for (int ci=0; ci<CH; ci++){
            const float* ru = su + ci*SROW + p0;
            float4 u0 = *(const float4*)ru;          // p0..p0+3 (aligned)
            float2 u1 = *(const float2*)(ru + 4);    // p0+4, p0+5
            float xv[6] = {u0.x, u0.y, u0.z, u0.w, u1.x, u1.y};
            #pragma unroll
            for (int co=0; co<CH; co++){
                const float w0 = sw[(co*CH+ci)*3 + 0];
                const float w1 = sw[(co*CH+ci)*3 + 1];
                const float w2 = sw[(co*CH+ci)*3 + 2];
                #pragma unroll
                for (int j=0; j<4; j++)
                    a[co][j] = fmaf(w0, xv[j], fmaf(w1, xv[j+1], fmaf(w2, xv[j+2], a[co][j])));
            }
        }
        // fold bias into cu
        #pragma unroll
        for (int co=0; co<CH; co++){
            const float bias = sb[co];
            #pragma unroll
            for (int j=0; j<4; j++){
                a[co][j] += bias;
                cu[co][j] = a[co][j];
            }
        }
    } else {
        // hoisted, batched edge loads (MLP)
        float xl[CH], xr[CH];
        #pragma unroll
        for (int ci=0; ci<CH; ci++){
            xl[ci] = eLr[ci*EDG + tid];
            xr[ci] = eRr[ci*EDG + tid + 1];
        }
        #pragma unroll
        for (int ci=0; ci<CH; ci++){
            float xvk[6];
            xvk[0] = xl[ci];
            xvk[1] = kr[ci][0]; xvk[2] = kr[ci][1];
            xvk[3] = kr[ci][2]; xvk[4] = kr[ci][3];
            xvk[5] = xr[ci];
            if (edge){
                #pragma unroll
                for (int j=0; j<6; j++)
                    if ((unsigned)(gofs + p0 + j) >= NPT) xvk[j] = 0.f;
            }
            #pragma unroll
            for (int co=0; co<CH; co++){
                const float w0 = sw[(co*CH+ci)*3 + 0];
                const float w1 = sw[(co*CH+ci)*3 + 1];
                const float w2 = sw[(co*CH+ci)*3 + 2];
                #pragma unroll
                for (int j=0; j<4; j++)
                    a[co][j] = fmaf(w0, xvk[j], fmaf(w1, xvk[j+1], fmaf(w2, xvk[j+2], a[co][j])));
            }
        }
        #pragma unroll
        for (int co=0; co<CH; co++)
            #pragma unroll
            for (int j=0; j<4; j++) a[co][j] = fmaf(cc, a[co][j], cu[co][j]);
    }

    #pragma unroll
    for (int co=0; co<CH; co++){
        #pragma unroll
        for (int j=0; j<4; j++){
            float t = htanh(a[co][j]);
            kr[co][j] = t;
            acc[co][j] = fmaf(aw, t, acc[co][j]);
        }
        if (S < 3){
            eLw[co*EDG + tid + 1] = kr[co][3];   // k(4t+4)
            eRw[co*EDG + tid]     = kr[co][0];   // k(4t+1)
        }
    }
    if (S < 3) __syncthreads();
}

// ---------------- fused 7-step RK4 kernel ----------------
__global__ void __launch_bounds__(RKTHREADS, 2)
rk4_fused(const float* __restrict__ src, float* __restrict__ dst,
          const float* __restrict__ t_span,
          const float* __restrict__ conv_w, const float* __restrict__ conv_b)
{
    extern __shared__ float sm[];
    float* s_su = sm;                      // CH*SROW
    float* s_eL = s_su + CH*SROW;          // 2*CH*EDG
    float* s_eR = s_eL + 2*CH*EDG;         // 2*CH*EDG
    float* s_ts = s_eR + 2*CH*EDG;         // TSTEPS
    float* s_w  = s_ts + TSTEPS;           // CH*CH*3 = 108
    float* s_b  = s_w + CH*CH*3;           // CH

    const int b    = blockIdx.y;
    const int bx   = blockIdx.x;
    const int gofs = bx*CORE - VMARG;
    const int tid  = threadIdx.x;
    const bool edge = (bx == 0) | (bx == gridDim.x - 1);
    const int p0 = 4*tid;

    if (tid < CH){
        s_eL[tid*EDG + 0] = 0.f;           // k(0) sentinels, both buffers
        s_eL[(CH+tid)*EDG + 0] = 0.f;
        s_eR[tid*EDG + 256] = 0.f;         // k(1025) sentinels, both buffers
        s_eR[(CH+tid)*EDG + 256] = 0.f;
        s_b[tid] = conv_b[tid];
    }
    if (tid < TSTEPS)  s_ts[tid] = t_span[tid];
    if (tid < CH*CH*3) s_w[tid]  = conv_w[tid];
    #pragma unroll
    for (int ch=0; ch<CH; ch++){
        const float* sc = src + ((size_t)b*CH + ch)*NPT;
        for (int p=tid; p<EXT; p+=RKTHREADS){
            int g = gofs + p;
            s_su[ch*SROW + p] = ((unsigned)g < NPT) ? sc[g] : 0.f;
        }
    }
    __syncthreads();

    float* eL0 = s_eL;  float* eL1 = s_eL + CH*EDG;
    float* eR0 = s_eR;  float* eR1 = s_eR + CH*EDG;

    #pragma unroll 1
    for (int s=0; s<TSTEPS-1; s++){
        const float dt  = s_ts[s+1] - s_ts[s];
        const float hdt = 0.5f*dt;

        float cu[CH][4], kr[CH][4], acc[CH][4];
        #pragma unroll
        for (int co=0; co<CH; co++){
            acc[co][0]=0.f; acc[co][1]=0.f; acc[co][2]=0.f; acc[co][3]=0.f;
        }

        stage<0>(cu, eL0,eR0, eL0,eR0, s_su, s_w, s_b, 0.f, 1.f, gofs, tid, edge, kr, acc);
        stage<1>(cu, eL0,eR0, eL1,eR1, s_su, s_w, s_b, hdt, 2.f, gofs, tid, edge, kr, acc);
        stage<2>(cu, eL1,eR1, eL0,eR0, s_su, s_w, s_b, hdt, 2.f, gofs, tid, edge, kr, acc);
        stage<3>(cu, eL0,eR0, eL1,eR1, s_su, s_w, s_b, dt,  1.f, gofs, tid, edge, kr, acc);

        // su update fused into stage-3 epilogue (stages 1-3 never read su)
        const float dt6 = dt * (1.0f/6.0f);
        #pragma unroll
        for (int co=0; co<CH; co++){
            float* rp = s_su + co*SROW;
            #pragma unroll
            for (int j=0; j<4; j++){
                int p = p0 + 1 + j;
                int g = gofs + p;
                if (!edge || (unsigned)g < NPT)
                    rp[p] += dt6 * acc[co][j];
            }
        }
        __syncthreads();            // updated su visible to next step's stage 0
    }

    // final store: valid core [29, 997)
    #pragma unroll
    for (int co=0; co<CH; co++){
        float* dp = dst + ((size_t)b*CH + co)*NPT;
        const float* rp = s_su + co*SROW;
        #pragma unroll
        for (int j=0; j<4; j++){
            int p = p0 + 1 + j;
            int g = gofs + p;
            if (p >= VMARG && p < EXT-VMARG && (unsigned)g < NPT)
                dp[g] = rp[p];
        }
    }
}

// ---------------- forward 16-mode DFT (partial sums) ----------------
__global__ void __launch_bounds__(256)
fwd_dft_kernel(const float* __restrict__ u)
{
    const int blk  = blockIdx.x;                 // [0, BB*CH*FBLK)
    const int seg  = blk & (FBLK-1);
    const int bi   = blk / FBLK;                 // b*CH + i
    const int tid  = threadIdx.x;
    const int lane = tid & 31, warp = tid >> 5;
    const int n0   = seg*8192 + warp*1024 + lane;  // stride-32 walk, coalesced
    const float* x = u + (size_t)bi*NPT;

    const float TWO_PI = 6.283185307179586f;
    float cr[MODES], cim[MODES], ck[MODES], sk[MODES], dc[MODES], ds[MODES];
    #pragma unroll
    for (int k=0; k<MODES; k++){
        cr[k]=0.f; cim[k]=0.f;
        float a0 = TWO_PI * ((float)((k*n0) & NMASK) * (1.0f/NPT));
        sincosf(a0, &sk[k], &ck[k]);
        float ad = TWO_PI * ((float)(k*32) * (1.0f/NPT));
        sincosf(ad, &ds[k], &dc[k]);
    }
    #pragma unroll 2
    for (int j=0; j<32; j++){
        float v = __ldg(&x[n0 + (j<<5)]);
        #pragma unroll
        for (int k=0; k<MODES; k++){
            cr[k]  = fmaf( v, ck[k], cr[k]);     // X += u * e^{-i theta}
            cim[k] = fmaf(-v, sk[k], cim[k]);
            float nc = ck[k]*dc[k] - sk[k]*ds[k];
            sk[k] = fmaf(ck[k], ds[k], sk[k]*dc[k]);
            ck[k] = nc;
        }
    }
    #pragma unroll
    for (int k=0; k<MODES; k++){
        #pragma unroll
        for (int off=16; off; off>>=1){
            cr[k]  += __shfl_xor_sync(0xffffffffu, cr[k],  off);
            cim[k] += __shfl_xor_sync(0xffffffffu, cim[k], off);
        }
    }
    __shared__ float red[8][MODES*2];
    if (lane == 0){
        #pragma unroll
        for (int k=0; k<MODES; k++){
            red[warp][2*k]   = cr[k];
            red[warp][2*k+1] = cim[k];
        }
    }
    __syncthreads();
    if (tid < MODES*2){
        float s = 0.f;
        #pragma unroll
        for (int w=0; w<8; w++) s += red[w][tid];
        g_part[(bi*FBLK + seg)*(MODES*2) + tid] = s;
    }
}

// ---------------- synthesis: fused mix + 16-mode irfft + bias ----------------
// Preamble (tid<96): recompute this batch's mode-mix from g_part (L2-resident)
// with proj folded in. 512 blocks (16 segs/batch) for latency spreading.
__global__ void __launch_bounds__(256)
synth_kernel(float* __restrict__ out,
             const float* __restrict__ sw_r, const float* __restrict__ sw_i,
             const float* __restrict__ proj_w, const float* __restrict__ proj_b)
{
    const int blk  = blockIdx.x;        // b*SSEG + seg
    const int b    = blk / SSEG, seg = blk % SSEG;
    const int tid  = threadIdx.x, lane = tid & 31, warp = tid >> 5;
    const int n0   = seg*4096 + warp*512 + lane;

    __shared__ float zz[CH*MODES*2];
    __shared__ float pb[CH];
    __shared__ float sdc[MODES], sds[MODES];   // thread-invariant rotation consts
    if (tid < CH*MODES){
        const int o = tid / MODES, k = tid % MODES;
        float Zr = 0.f, Zi = 0.f;
        #pragma unroll
        for (int i=0; i<CH; i++){
            float Xr=0.f, Xi=0.f;
            int bi = b*CH + i;
            #pragma unroll
            for (int s=0; s<FBLK; s++){
                Xr += g_part[(bi*FBLK+s)*(MODES*2) + 2*k];
                Xi += g_part[(bi*FBLK+s)*(MODES*2) + 2*k + 1];
            }
            float Wr=0.f, Wi=0.f;
            #pragma unroll
            for (int c=0; c<CH; c++){
                float pw = proj_w[o*CH + c];
                Wr = fmaf(sw_r[(i*CH+c)*MODES + k], pw, Wr);
                Wi = fmaf(sw_i[(i*CH+c)*MODES + k], pw, Wi);
            }
            Zr += Xr*Wr - Xi*Wi;
            Zi += Xr*Wi + Xi*Wr;
        }
        float scale = (k==0) ? (1.0f/NPT) : (2.0f/NPT);   // irfft: DC once, others doubled
        zz[(o*MODES+k)*2]     = Zr*scale;
        zz[(o*MODES+k)*2 + 1] = Zi*scale;
    }
    if (tid < CH) pb[tid] = proj_b[tid];
    if (tid >= 128 && tid < 128 + MODES){
        int k = tid - 128;
        float ad = 6.283185307179586f * ((float)(k*32) * (1.0f/NPT));
        float s, c; sincosf(ad, &s, &c);
        sds[k] = s; sdc[k] = c;
    }
    __syncthreads();

    const float TWO_PI = 6.283185307179586f;
    float ck[MODES], sk[MODES];
    #pragma unroll
    for (int k=0; k<MODES; k++){
        float a0 = TWO_PI * ((float)((k*n0) & NMASK) * (1.0f/NPT));
        sincosf(a0, &sk[k], &ck[k]);
    }
    #pragma unroll 1
    for (int j=0; j<16; j++){
        int n = n0 + (j<<5);
        float accv[CH];
        #pragma unroll
        for (int o=0; o<CH; o++) accv[o] = pb[o];
        #pragma unroll
        for (int k=0; k<MODES; k++){
            float c = ck[k], s = sk[k];
            #pragma unroll
            for (int o=0; o<CH; o++){
                accv[o] = fmaf( zz[(o*MODES+k)*2],     c, accv[o]);
                accv[o] = fmaf(-zz[(o*MODES+k)*2 + 1], s, accv[o]);
            }
            float dck = sdc[k], dsk = sds[k];
            float nc = c*dck - s*dsk;
            sk[k] = fmaf(c, dsk, s*dck);
            ck[k] = nc;
        }
        #pragma unroll
        for (int o=0; o<CH; o++)
            out[((size_t)(b*CH + o))*NPT + n] = accv[o];
    }
}

// ---------------- launch ----------------
extern "C" void kernel_launch(void* const* d_in, const int* in_sizes, int n_in,
                              void* d_out, int out_size)
{
    const float* u0     = (const float*)d_in[0];
    const float* t_span = (const float*)d_in[1];
    const float* conv_w = (const float*)d_in[2];
    const float* conv_b = (const float*)d_in[3];
    const float* sw_r   = (const float*)d_in[4];
    const float* sw_i   = (const float*)d_in[5];
    const float* proj_w = (const float*)d_in[6];
    const float* proj_b = (const float*)d_in[7];
    float* out = (float*)d_out;

    float* bufA = nullptr;
    cudaGetSymbolAddress((void**)&bufA, g_bufA);

    const int rk_smem = (CH*SROW + 4*CH*EDG + TSTEPS + CH*CH*3 + CH) * sizeof(float);
    cudaFuncSetAttribute(rk4_fused, cudaFuncAttributeMaxDynamicSharedMemorySize, rk_smem);

    dim3 rkgrid(NBLK, BB);
    rk4_fused<<<rkgrid, RKTHREADS, rk_smem>>>(u0, bufA, t_span, conv_w, conv_b);

    fwd_dft_kernel<<<BB*CH*FBLK, 256>>>(bufA);
    synth_kernel<<<BB*SSEG, 256>>>(out, sw_r, sw_i, proj_w, proj_b);
}

// round 15
// speedup vs baseline: 1.0503x; 1.0503x over previous
#include <cuda_runtime.h>

#define CH 6
#define MODES 16
#define BB 32
#define NPT 65536
#define NMASK 65535
#define TSTEPS 8

#define EXT 1026                 // logical window: indices 0..1025
#define SROW 1032                // padded row stride (float4 alignment)
#define VMARG 29                 // validity margin after 28 stage-shrinks (+1 end)
#define CORE 968                 // EXT - 2*VMARG, valid output core [29, 997)
#define NBLK 68                  // 68*968 = 65824 >= NPT
#define RKTHREADS 256            // 4 points/thread tile [1,1025) exactly
#define EDG 260                  // per-channel stride in edge arrays
#define FBLK 8                   // blocks per (b,i) in forward DFT

// -------- scratch (no allocations allowed) --------
__device__ float g_bufA[BB*CH*NPT];
__device__ float g_part[BB*CH*FBLK*MODES*2];

__device__ __forceinline__ float htanh(float x){
    float y;
    asm("tanh.approx.f32 %0, %1;" : "=f"(y) : "f"(x));
    return y;
}

// ---------------- stage ----------------
// 4 points/thread: own p0+1..p0+4 (p0=4*tid), window [p0, p0+5]; threads tile
// [1,1025) exactly — NO tail. Linearity split: cu = conv(u)+bias (stage 0);
// stages 1-3: a = cu + cc*conv(k). Weights/bias in SMEM (broadcast LDS).
// Edge arrays (double-buffered, stride-1): eL[i]=k(4i) (i=0 sentinel),
// eR[i]=k(4i+1) (i=256 sentinel). Stages 1-3 read ONLY edges/kr (not su).

template<int S>
__device__ __forceinline__ void stage(
    float (&cu)[CH][4],
    const float* __restrict__ eLr, const float* __restrict__ eRr,
    float* __restrict__ eLw, float* __restrict__ eRw,
    const float* __restrict__ su,
    const float* __restrict__ sw, const float* __restrict__ sb,
    float cc, float aw, int gofs, int tid, bool edge,
    float (&kr)[CH][4], float (&acc)[CH][4])
{
    const int p0 = 4*tid;
    float a[CH][4];
    #pragma unroll
    for (int co=0; co<CH; co++){ a[co][0]=0.f; a[co][1]=0.f; a[co][2]=0.f; a[co][3]=0.f; }

    if (S == 0){
        #pragma unroll
        for (int ci=0; ci<CH; ci++){
            const float* ru = su + ci*SROW + p0;
            float4 u0 = *(const float4*)ru;          // p0..p0+3 (aligned)
            float2 u1 = *(const float2*)(ru + 4);    // p0+4, p0+5
            float xv[6] = {u0.x, u0.y, u0.z, u0.w, u1.x, u1.y};
            #pragma unroll
            for (int co=0; co<CH; co++){
                const float w0 = sw[(co*CH+ci)*3 + 0];
                const float w1 = sw[(co*CH+ci)*3 + 1];
                const float w2 = sw[(co*CH+ci)*3 + 2];
                #pragma unroll
                for (int j=0; j<4; j++)
                    a[co][j] = fmaf(w0, xv[j], fmaf(w1, xv[j+1], fmaf(w2, xv[j+2], a[co][j])));
            }
        }
        // fold bias into cu
        #pragma unroll
        for (int co=0; co<CH; co++){
            const float bias = sb[co];
            #pragma unroll
            for (int j=0; j<4; j++){
                a[co][j] += bias;
                cu[co][j] = a[co][j];
            }
        }
    } else {
        // hoisted, batched edge loads (MLP)
        float xl[CH], xr[CH];
        #pragma unroll
        for (int ci=0; ci<CH; ci++){
            xl[ci] = eLr[ci*EDG + tid];
            xr[ci] = eRr[ci*EDG + tid + 1];
        }
        #pragma unroll
        for (int ci=0; ci<CH; ci++){
            float xvk[6];
            xvk[0] = xl[ci];
            xvk[1] = kr[ci][0]; xvk[2] = kr[ci][1];
            xvk[3] = kr[ci][2]; xvk[4] = kr[ci][3];
            xvk[5] = xr[ci];
            if (edge){
                #pragma unroll
                for (int j=0; j<6; j++)
                    if ((unsigned)(gofs + p0 + j) >= NPT) xvk[j] = 0.f;
            }
            #pragma unroll
            for (int co=0; co<CH; co++){
                const float w0 = sw[(co*CH+ci)*3 + 0];
                const float w1 = sw[(co*CH+ci)*3 + 1];
                const float w2 = sw[(co*CH+ci)*3 + 2];
                #pragma unroll
                for (int j=0; j<4; j++)
                    a[co][j] = fmaf(w0, xvk[j], fmaf(w1, xvk[j+1], fmaf(w2, xvk[j+2], a[co][j])));
            }
        }
        #pragma unroll
        for (int co=0; co<CH; co++)
            #pragma unroll
            for (int j=0; j<4; j++) a[co][j] = fmaf(cc, a[co][j], cu[co][j]);
    }

    #pragma unroll
    for (int co=0; co<CH; co++){
        #pragma unroll
        for (int j=0; j<4; j++){
            float t = htanh(a[co][j]);
            kr[co][j] = t;
            acc[co][j] = fmaf(aw, t, acc[co][j]);
        }
        if (S < 3){
            eLw[co*EDG + tid + 1] = kr[co][3];   // k(4t+4)
            eRw[co*EDG + tid]     = kr[co][0];   // k(4t+1)
        }
    }
    if (S < 3) __syncthreads();
}

// ---------------- fused 7-step RK4 kernel ----------------
__global__ void __launch_bounds__(RKTHREADS, 2)
rk4_fused(const float* __restrict__ src, float* __restrict__ dst,
          const float* __restrict__ t_span,
          const float* __restrict__ conv_w, const float* __restrict__ conv_b)
{
    extern __shared__ float sm[];
    float* s_su = sm;                      // CH*SROW
    float* s_eL = s_su + CH*SROW;          // 2*CH*EDG
    float* s_eR = s_eL + 2*CH*EDG;         // 2*CH*EDG
    float* s_ts = s_eR + 2*CH*EDG;         // TSTEPS
    float* s_w  = s_ts + TSTEPS;           // CH*CH*3 = 108
    float* s_b  = s_w + CH*CH*3;           // CH

    const int b    = blockIdx.y;
    const int bx   = blockIdx.x;
    const int gofs = bx*CORE - VMARG;
    const int tid  = threadIdx.x;
    const bool edge = (bx == 0) | (bx == gridDim.x - 1);
    const int p0 = 4*tid;

    if (tid < CH){
        s_eL[tid*EDG + 0] = 0.f;           // k(0) sentinels, both buffers
        s_eL[(CH+tid)*EDG + 0] = 0.f;
        s_eR[tid*EDG + 256] = 0.f;         // k(1025) sentinels, both buffers
        s_eR[(CH+tid)*EDG + 256] = 0.f;
        s_b[tid] = conv_b[tid];
    }
    if (tid < TSTEPS)  s_ts[tid] = t_span[tid];
    if (tid < CH*CH*3) s_w[tid]  = conv_w[tid];
    #pragma unroll
    for (int ch=0; ch<CH; ch++){
        const float* sc = src + ((size_t)b*CH + ch)*NPT;
        for (int p=tid; p<EXT; p+=RKTHREADS){
            int g = gofs + p;
            s_su[ch*SROW + p] = ((unsigned)g < NPT) ? sc[g] : 0.f;
        }
    }
    __syncthreads();

    float* eL0 = s_eL;  float* eL1 = s_eL + CH*EDG;
    float* eR0 = s_eR;  float* eR1 = s_eR + CH*EDG;

    #pragma unroll 1
    for (int s=0; s<TSTEPS-1; s++){
        const float dt  = s_ts[s+1] - s_ts[s];
        const float hdt = 0.5f*dt;

        float cu[CH][4], kr[CH][4], acc[CH][4];
        #pragma unroll
        for (int co=0; co<CH; co++){
            acc[co][0]=0.f; acc[co][1]=0.f; acc[co][2]=0.f; acc[co][3]=0.f;
        }

        stage<0>(cu, eL0,eR0, eL0,eR0, s_su, s_w, s_b, 0.f, 1.f, gofs, tid, edge, kr, acc);
        stage<1>(cu, eL0,eR0, eL1,eR1, s_su, s_w, s_b, hdt, 2.f, gofs, tid, edge, kr, acc);
        stage<2>(cu, eL1,eR1, eL0,eR0, s_su, s_w, s_b, hdt, 2.f, gofs, tid, edge, kr, acc);
        stage<3>(cu, eL0,eR0, eL1,eR1, s_su, s_w, s_b, dt,  1.f, gofs, tid, edge, kr, acc);

        // su update fused into stage-3 epilogue (stages 1-3 never read su)
        const float dt6 = dt * (1.0f/6.0f);
        #pragma unroll
        for (int co=0; co<CH; co++){
            float* rp = s_su + co*SROW;
            #pragma unroll
            for (int j=0; j<4; j++){
                int p = p0 + 1 + j;
                int g = gofs + p;
                if (!edge || (unsigned)g < NPT)
                    rp[p] += dt6 * acc[co][j];
            }
        }
        __syncthreads();            // updated su visible to next step's stage 0
    }

    // final store: valid core [29, 997)
    #pragma unroll
    for (int co=0; co<CH; co++){
        float* dp = dst + ((size_t)b*CH + co)*NPT;
        const float* rp = s_su + co*SROW;
        #pragma unroll
        for (int j=0; j<4; j++){
            int p = p0 + 1 + j;
            int g = gofs + p;
            if (p >= VMARG && p < EXT-VMARG && (unsigned)g < NPT)
                dp[g] = rp[p];
        }
    }
}

// ---------------- forward 16-mode DFT (partial sums) ----------------
__global__ void __launch_bounds__(256)
fwd_dft_kernel(const float* __restrict__ u)
{
    const int blk  = blockIdx.x;                 // [0, BB*CH*FBLK)
    const int seg  = blk & (FBLK-1);
    const int bi   = blk / FBLK;                 // b*CH + i
    const int tid  = threadIdx.x;
    const int lane = tid & 31, warp = tid >> 5;
    const int n0   = seg*8192 + warp*1024 + lane;  // stride-32 walk, coalesced
    const float* x = u + (size_t)bi*NPT;

    const float TWO_PI = 6.283185307179586f;
    float cr[MODES], cim[MODES], ck[MODES], sk[MODES], dc[MODES], ds[MODES];
    #pragma unroll
    for (int k=0; k<MODES; k++){
        cr[k]=0.f; cim[k]=0.f;
        float a0 = TWO_PI * ((float)((k*n0) & NMASK) * (1.0f/NPT));
        sincosf(a0, &sk[k], &ck[k]);
        float ad = TWO_PI * ((float)(k*32) * (1.0f/NPT));
        sincosf(ad, &ds[k], &dc[k]);
    }
    #pragma unroll 2
    for (int j=0; j<32; j++){
        float v = __ldg(&x[n0 + (j<<5)]);
        #pragma unroll
        for (int k=0; k<MODES; k++){
            cr[k]  = fmaf( v, ck[k], cr[k]);     // X += u * e^{-i theta}
            cim[k] = fmaf(-v, sk[k], cim[k]);
            float nc = ck[k]*dc[k] - sk[k]*ds[k];
            sk[k] = fmaf(ck[k], ds[k], sk[k]*dc[k]);
            ck[k] = nc;
        }
    }
    #pragma unroll
    for (int k=0; k<MODES; k++){
        #pragma unroll
        for (int off=16; off; off>>=1){
            cr[k]  += __shfl_xor_sync(0xffffffffu, cr[k],  off);
            cim[k] += __shfl_xor_sync(0xffffffffu, cim[k], off);
        }
    }
    __shared__ float red[8][MODES*2];
    if (lane == 0){
        #pragma unroll
        for (int k=0; k<MODES; k++){
            red[warp][2*k]   = cr[k];
            red[warp][2*k+1] = cim[k];
        }
    }
    __syncthreads();
    if (tid < MODES*2){
        float s = 0.f;
        #pragma unroll
        for (int w=0; w<8; w++) s += red[w][tid];
        g_part[(bi*FBLK + seg)*(MODES*2) + tid] = s;
    }
}

// ---------------- synthesis: fused mix + 16-mode irfft + bias (R11 proven) ----------------
__global__ void __launch_bounds__(256)
synth_kernel(float* __restrict__ out,
             const float* __restrict__ sw_r, const float* __restrict__ sw_i,
             const float* __restrict__ proj_w, const float* __restrict__ proj_b)
{
    const int blk  = blockIdx.x;        // b*8 + seg
    const int b    = blk >> 3, seg = blk & 7;
    const int tid  = threadIdx.x, lane = tid & 31, warp = tid >> 5;
    const int n0   = seg*8192 + warp*1024 + lane;

    __shared__ float zz[CH*MODES*2];
    __shared__ float pb[CH];
    if (tid < CH*MODES){
        const int o = tid / MODES, k = tid % MODES;
        float Zr = 0.f, Zi = 0.f;
        #pragma unroll
        for (int i=0; i<CH; i++){
            float Xr=0.f, Xi=0.f;
            int bi = b*CH + i;
            #pragma unroll
            for (int s=0; s<FBLK; s++){
                Xr += g_part[(bi*FBLK+s)*(MODES*2) + 2*k];
                Xi += g_part[(bi*FBLK+s)*(MODES*2) + 2*k + 1];
            }
            float Wr=0.f, Wi=0.f;
            #pragma unroll
            for (int c=0; c<CH; c++){
                float pw = proj_w[o*CH + c];
                Wr = fmaf(sw_r[(i*CH+c)*MODES + k], pw, Wr);
                Wi = fmaf(sw_i[(i*CH+c)*MODES + k], pw, Wi);
            }
            Zr += Xr*Wr - Xi*Wi;
            Zi += Xr*Wi + Xi*Wr;
        }
        float scale = (k==0) ? (1.0f/NPT) : (2.0f/NPT);   // irfft: DC once, others doubled
        zz[(o*MODES+k)*2]     = Zr*scale;
        zz[(o*MODES+k)*2 + 1] = Zi*scale;
    }
    if (tid < CH) pb[tid] = proj_b[tid];
    __syncthreads();

    const float TWO_PI = 6.283185307179586f;
    float ck[MODES], sk[MODES], dc[MODES], ds[MODES];
    #pragma unroll
    for (int k=0; k<MODES; k++){
        float a0 = TWO_PI * ((float)((k*n0) & NMASK) * (1.0f/NPT));
        sincosf(a0, &sk[k], &ck[k]);
        float ad = TWO_PI * ((float)(k*32) * (1.0f/NPT));
        sincosf(ad, &ds[k], &dc[k]);
    }
    for (int j=0; j<32; j++){
        int n = n0 + (j<<5);
        float accv[CH];
        #pragma unroll
        for (int o=0; o<CH; o++) accv[o] = pb[o];
        #pragma unroll
        for (int k=0; k<MODES; k++){
            float c = ck[k], s = sk[k];
            #pragma unroll
            for (int o=0; o<CH; o++){
                accv[o] = fmaf( zz[(o*MODES+k)*2],     c, accv[o]);
                accv[o] = fmaf(-zz[(o*MODES+k)*2 + 1], s, accv[o]);
            }
            float nc = c*dc[k] - s*ds[k];
            sk[k] = fmaf(c, ds[k], s*dc[k]);
            ck[k] = nc;
        }
        #pragma unroll
        for (int o=0; o<CH; o++)
            out[((size_t)(b*CH + o))*NPT + n] = accv[o];
    }
}

// ---------------- launch ----------------
extern "C" void kernel_launch(void* const* d_in, const int* in_sizes, int n_in,
                              void* d_out, int out_size)
{
    const float* u0     = (const float*)d_in[0];
    const float* t_span = (const float*)d_in[1];
    const float* conv_w = (const float*)d_in[2];
    const float* conv_b = (const float*)d_in[3];
    const float* sw_r   = (const float*)d_in[4];
    const float* sw_i   = (const float*)d_in[5];
    const float* proj_w = (const float*)d_in[6];
    const float* proj_b = (const float*)d_in[7];
    float* out = (float*)d_out;

    float* bufA = nullptr;
    cudaGetSymbolAddress((void**)&bufA, g_bufA);

    const int rk_smem = (CH*SROW + 4*CH*EDG + TSTEPS + CH*CH*3 + CH) * sizeof(float);
    cudaFuncSetAttribute(rk4_fused, cudaFuncAttributeMaxDynamicSharedMemorySize, rk_smem);

    dim3 rkgrid(NBLK, BB);
    rk4_fused<<<rkgrid, RKTHREADS, rk_smem>>>(u0, bufA, t_span, conv_w, conv_b);

    fwd_dft_kernel<<<BB*CH*FBLK, 256>>>(bufA);
    synth_kernel<<<BB*8, 256>>>(out, sw_r, sw_i, proj_w, proj_b);
}

// round 16
// speedup vs baseline: 1.1109x; 1.0577x over previous
#include <cuda_runtime.h>

#define CH 6
#define MODES 16
#define BB 32
#define NPT 65536
#define NMASK 65535
#define TSTEPS 8

#define EXT 1026                 // logical window: indices 0..1025
#define SROW 1032                // padded row stride (float4 alignment)
#define VMARG 29                 // validity margin after 28 stage-shrinks (+1 end)
#define CORE 968                 // EXT - 2*VMARG, valid output core [29, 997)
#define NBLK 68                  // 68*968 = 65824 >= NPT
#define RKTHREADS 256            // 4 points/thread tile [1,1025) exactly
#define EDG 260                  // per-channel stride in edge arrays
#define FBLK 8                   // blocks per (b,i) in forward DFT

// -------- scratch (no allocations allowed) --------
__device__ float g_bufA[BB*CH*NPT];
__device__ float g_part[BB*CH*FBLK*MODES*2];

__device__ __forceinline__ float htanh(float x){
    float y;
    asm("tanh.approx.f32 %0, %1;" : "=f"(y) : "f"(x));
    return y;
}

// ---------------- stage ----------------
// 4 points/thread: own p0+1..p0+4 (p0=4*tid), window [p0, p0+5]; threads tile
// [1,1025) exactly — NO tail. Linearity split: cu = conv(u)+bias (stage 0);
// stages 1-3: a = cu + cc*conv(k). Weights/bias in SMEM (broadcast LDS).
// Edge arrays (double-buffered, stride-1): eL[i]=k(4i) (i=0 sentinel),
// eR[i]=k(4i+1) (i=256 sentinel). Stages 1-3 read ONLY edges/kr (not su).

template<int S>
__device__ __forceinline__ void stage(
    float (&cu)[CH][4],
    const float* __restrict__ eLr, const float* __restrict__ eRr,
    float* __restrict__ eLw, float* __restrict__ eRw,
    const float* __restrict__ su,
    const float* __restrict__ sw, const float* __restrict__ sb,
    float cc, float aw, int gofs, int tid, bool edge,
    float (&kr)[CH][4], float (&acc)[CH][4])
{
    const int p0 = 4*tid;
    float a[CH][4];
    #pragma unroll
    for (int co=0; co<CH; co++){ a[co][0]=0.f; a[co][1]=0.f; a[co][2]=0.f; a[co][3]=0.f; }

    if (S == 0){
        #pragma unroll
        for (int ci=0; ci<CH; ci++){
            const float* ru = su + ci*SROW + p0;
            float4 u0 = *(const float4*)ru;          // p0..p0+3 (aligned)
            float2 u1 = *(const float2*)(ru + 4);    // p0+4, p0+5
            float xv[6] = {u0.x, u0.y, u0.z, u0.w, u1.x, u1.y};
            #pragma unroll
            for (int co=0; co<CH; co++){
                const float w0 = sw[(co*CH+ci)*3 + 0];
                const float w1 = sw[(co*CH+ci)*3 + 1];
                const float w2 = sw[(co*CH+ci)*3 + 2];
                #pragma unroll
                for (int j=0; j<4; j++)
                    a[co][j] = fmaf(w0, xv[j], fmaf(w1, xv[j+1], fmaf(w2, xv[j+2], a[co][j])));
            }
        }
        // fold bias into cu
        #pragma unroll
        for (int co=0; co<CH; co++){
            const float bias = sb[co];
            #pragma unroll
            for (int j=0; j<4; j++){
                a[co][j] += bias;
                cu[co][j] = a[co][j];
            }
        }
    } else {
        // hoisted, batched edge loads (MLP)
        float xl[CH], xr[CH];
        #pragma unroll
        for (int ci=0; ci<CH; ci++){
            xl[ci] = eLr[ci*EDG + tid];
            xr[ci] = eRr[ci*EDG + tid + 1];
        }
        #pragma unroll
        for (int ci=0; ci<CH; ci++){
            float xvk[6];
            xvk[0] = xl[ci];
            xvk[1] = kr[ci][0]; xvk[2] = kr[ci][1];
            xvk[3] = kr[ci][2]; xvk[4] = kr[ci][3];
            xvk[5] = xr[ci];
            if (edge){
                #pragma unroll
                for (int j=0; j<6; j++)
                    if ((unsigned)(gofs + p0 + j) >= NPT) xvk[j] = 0.f;
            }
            #pragma unroll
            for (int co=0; co<CH; co++){
                const float w0 = sw[(co*CH+ci)*3 + 0];
                const float w1 = sw[(co*CH+ci)*3 + 1];
                const float w2 = sw[(co*CH+ci)*3 + 2];
                #pragma unroll
                for (int j=0; j<4; j++)
                    a[co][j] = fmaf(w0, xvk[j], fmaf(w1, xvk[j+1], fmaf(w2, xvk[j+2], a[co][j])));
            }
        }
        #pragma unroll
        for (int co=0; co<CH; co++)
            #pragma unroll
            for (int j=0; j<4; j++) a[co][j] = fmaf(cc, a[co][j], cu[co][j]);
    }

    #pragma unroll
    for (int co=0; co<CH; co++){
        #pragma unroll
        for (int j=0; j<4; j++){
            float t = htanh(a[co][j]);
            kr[co][j] = t;
            acc[co][j] = fmaf(aw, t, acc[co][j]);
        }
        if (S < 3){
            eLw[co*EDG + tid + 1] = kr[co][3];   // k(4t+4)
            eRw[co*EDG + tid]     = kr[co][0];   // k(4t+1)
        }
    }
    if (S < 3) __syncthreads();
}

// ---------------- fused 7-step RK4 kernel ----------------
__global__ void __launch_bounds__(RKTHREADS, 2)
rk4_fused(const float* __restrict__ src, float* __restrict__ dst,
          const float* __restrict__ t_span,
          const float* __restrict__ conv_w, const float* __restrict__ conv_b)
{
    extern __shared__ float sm[];
    float* s_su   = sm;                      // CH*SROW
    float* s_eL   = s_su + CH*SROW;          // 2*CH*EDG
    float* s_eR   = s_eL + 2*CH*EDG;         // 2*CH*EDG
    float* s_ts   = s_eR + 2*CH*EDG;         // TSTEPS
    float* s_w    = s_ts + TSTEPS;           // CH*CH*3 = 108
    float* s_b    = s_w + CH*CH*3;           // CH
    float* s_hand = s_b + CH;                // CH*8 warp-boundary acc handoff

    const int b    = blockIdx.y;
    const int bx   = blockIdx.x;
    const int gofs = bx*CORE - VMARG;
    const int tid  = threadIdx.x;
    const bool edge = (bx == 0) | (bx == gridDim.x - 1);
    const int p0   = 4*tid;
    const int lane = tid & 31;
    const int wid  = tid >> 5;

    if (tid < CH){
        s_eL[tid*EDG + 0] = 0.f;           // k(0) sentinels, both buffers
        s_eL[(CH+tid)*EDG + 0] = 0.f;
        s_eR[tid*EDG + 256] = 0.f;         // k(1025) sentinels, both buffers
        s_eR[(CH+tid)*EDG + 256] = 0.f;
        s_b[tid] = conv_b[tid];
    }
    if (tid < TSTEPS)  s_ts[tid] = t_span[tid];
    if (tid < CH*CH*3) s_w[tid]  = conv_w[tid];
    #pragma unroll
    for (int ch=0; ch<CH; ch++){
        const float* sc = src + ((size_t)b*CH + ch)*NPT;
        for (int p=tid; p<EXT; p+=RKTHREADS){
            int g = gofs + p;
            s_su[ch*SROW + p] = ((unsigned)g < NPT) ? sc[g] : 0.f;
        }
    }
    __syncthreads();

    float* eL0 = s_eL;  float* eL1 = s_eL + CH*EDG;
    float* eR0 = s_eR;  float* eR1 = s_eR + CH*EDG;

    #pragma unroll 1
    for (int s=0; s<TSTEPS-1; s++){
        const float dt  = s_ts[s+1] - s_ts[s];
        const float hdt = 0.5f*dt;

        float cu[CH][4], kr[CH][4], acc[CH][4];
        #pragma unroll
        for (int co=0; co<CH; co++){
            acc[co][0]=0.f; acc[co][1]=0.f; acc[co][2]=0.f; acc[co][3]=0.f;
        }

        stage<0>(cu, eL0,eR0, eL0,eR0, s_su, s_w, s_b, 0.f, 1.f, gofs, tid, edge, kr, acc);
        stage<1>(cu, eL0,eR0, eL1,eR1, s_su, s_w, s_b, hdt, 2.f, gofs, tid, edge, kr, acc);
        stage<2>(cu, eL1,eR1, eL0,eR0, s_su, s_w, s_b, hdt, 2.f, gofs, tid, edge, kr, acc);
        stage<3>(cu, eL0,eR0, eL1,eR1, s_su, s_w, s_b, dt,  1.f, gofs, tid, edge, kr, acc);

        // warp-boundary handoff: warp w lane 31 publishes acc[3] (point 128w+128)
        if (lane == 31){
            #pragma unroll
            for (int co=0; co<CH; co++) s_hand[co*8 + wid] = acc[co][3];
        }
        __syncthreads();

        // conflict-free epilogue: thread t RMWs aligned quad [4t, 4t+4).
        // Point 4t's acc comes from neighbor t-1 (shfl_up / handoff array).
        // Points 0 (garbage-but-finite) and 1024,1025 (stale) are inside the
        // 29-point discard margin. Edge blocks select 0 for OOB components,
        // preserving the zero-pad invariant exactly as skip-write did.
        const float dt6 = dt * (1.0f/6.0f);
        #pragma unroll
        for (int co=0; co<CH; co++){
            float ap = __shfl_up_sync(0xffffffffu, acc[co][3], 1);
            if (lane == 0 && wid > 0) ap = s_hand[co*8 + wid - 1];
            float* rp = s_su + co*SROW + p0;
            float4 v = *(const float4*)rp;
            float n0 = fmaf(dt6, ap,         v.x);
            float n1 = fmaf(dt6, acc[co][0], v.y);
            float n2 = fmaf(dt6, acc[co][1], v.z);
            float n3 = fmaf(dt6, acc[co][2], v.w);
            if (edge){
                n0 = ((unsigned)(gofs + p0 + 0) < NPT) ? n0 : 0.f;
                n1 = ((unsigned)(gofs + p0 + 1) < NPT) ? n1 : 0.f;
                n2 = ((unsigned)(gofs + p0 + 2) < NPT) ? n2 : 0.f;
                n3 = ((unsigned)(gofs + p0 + 3) < NPT) ? n3 : 0.f;
            }
            *(float4*)rp = make_float4(n0, n1, n2, n3);
        }
        __syncthreads();            // updated su visible to next step's stage 0
    }

    // final store: valid core [29, 997)
    #pragma unroll
    for (int co=0; co<CH; co++){
        float* dp = dst + ((size_t)b*CH + co)*NPT;
        const float* rp = s_su + co*SROW;
        #pragma unroll
        for (int j=0; j<4; j++){
            int p = p0 + 1 + j;
            int g = gofs + p;
            if (p >= VMARG && p < EXT-VMARG && (unsigned)g < NPT)
                dp[g] = rp[p];
        }
    }
}

// ---------------- forward 16-mode DFT (partial sums) ----------------
__global__ void __launch_bounds__(256)
fwd_dft_kernel(const float* __restrict__ u)
{
    const int blk  = blockIdx.x;                 // [0, BB*CH*FBLK)
    const int seg  = blk & (FBLK-1);
    const int bi   = blk / FBLK;                 // b*CH + i
    const int tid  = threadIdx.x;
    const int lane = tid & 31, warp = tid >> 5;
    const int n0   = seg*8192 + warp*1024 + lane;  // stride-32 walk, coalesced
    const float* x = u + (size_t)bi*NPT;

    const float TWO_PI = 6.283185307179586f;
    float cr[MODES], cim[MODES], ck[MODES], sk[MODES], dc[MODES], ds[MODES];
    #pragma unroll
    for (int k=0; k<MODES; k++){
        cr[k]=0.f; cim[k]=0.f;
        float a0 = TWO_PI * ((float)((k*n0) & NMASK) * (1.0f/NPT));
        sincosf(a0, &sk[k], &ck[k]);
        float ad = TWO_PI * ((float)(k*32) * (1.0f/NPT));
        sincosf(ad, &ds[k], &dc[k]);
    }
    #pragma unroll 2
    for (int j=0; j<32; j++){
        float v = __ldg(&x[n0 + (j<<5)]);
        #pragma unroll
        for (int k=0; k<MODES; k++){
            cr[k]  = fmaf( v, ck[k], cr[k]);     // X += u * e^{-i theta}
            cim[k] = fmaf(-v, sk[k], cim[k]);
            float nc = ck[k]*dc[k] - sk[k]*ds[k];
            sk[k] = fmaf(ck[k], ds[k], sk[k]*dc[k]);
            ck[k] = nc;
        }
    }
    #pragma unroll
    for (int k=0; k<MODES; k++){
        #pragma unroll
        for (int off=16; off; off>>=1){
            cr[k]  += __shfl_xor_sync(0xffffffffu, cr[k],  off);
            cim[k] += __shfl_xor_sync(0xffffffffu, cim[k], off);
        }
    }
    __shared__ float red[8][MODES*2];
    if (lane == 0){
        #pragma unroll
        for (int k=0; k<MODES; k++){
            red[warp][2*k]   = cr[k];
            red[warp][2*k+1] = cim[k];
        }
    }
    __syncthreads();
    if (tid < MODES*2){
        float s = 0.f;
        #pragma unroll
        for (int w=0; w<8; w++) s += red[w][tid];
        g_part[(bi*FBLK + seg)*(MODES*2) + tid] = s;
    }
}

// ---------------- synthesis: fused mix + 16-mode irfft + bias (R11 proven) ----------------
__global__ void __launch_bounds__(256)
synth_kernel(float* __restrict__ out,
             const float* __restrict__ sw_r, const float* __restrict__ sw_i,
             const float* __restrict__ proj_w, const float* __restrict__ proj_b)
{
    const int blk  = blockIdx.x;        // b*8 + seg
    const int b    = blk >> 3, seg = blk & 7;
    const int tid  = threadIdx.x, lane = tid & 31, warp = tid >> 5;
    const int n0   = seg*8192 + warp*1024 + lane;

    __shared__ float zz[CH*MODES*2];
    __shared__ float pb[CH];
    if (tid < CH*MODES){
        const int o = tid / MODES, k = tid % MODES;
        float Zr = 0.f, Zi = 0.f;
        #pragma unroll
        for (int i=0; i<CH; i++){
            float Xr=0.f, Xi=0.f;
            int bi = b*CH + i;
            #pragma unroll
            for (int s=0; s<FBLK; s++){
                Xr += g_part[(bi*FBLK+s)*(MODES*2) + 2*k];
                Xi += g_part[(bi*FBLK+s)*(MODES*2) + 2*k + 1];
            }
            float Wr=0.f, Wi=0.f;
            #pragma unroll
            for (int c=0; c<CH; c++){
                float pw = proj_w[o*CH + c];
                Wr = fmaf(sw_r[(i*CH+c)*MODES + k], pw, Wr);
                Wi = fmaf(sw_i[(i*CH+c)*MODES + k], pw, Wi);
            }
            Zr += Xr*Wr - Xi*Wi;
            Zi += Xr*Wi + Xi*Wr;
        }
        float scale = (k==0) ? (1.0f/NPT) : (2.0f/NPT);   // irfft: DC once, others doubled
        zz[(o*MODES+k)*2]     = Zr*scale;
        zz[(o*MODES+k)*2 + 1] = Zi*scale;
    }
    if (tid < CH) pb[tid] = proj_b[tid];
    __syncthreads();

    const float TWO_PI = 6.283185307179586f;
    float ck[MODES], sk[MODES], dc[MODES], ds[MODES];
    #pragma unroll
    for (int k=0; k<MODES; k++){
        float a0 = TWO_PI * ((float)((k*n0) & NMASK) * (1.0f/NPT));
        sincosf(a0, &sk[k], &ck[k]);
        float ad = TWO_PI * ((float)(k*32) * (1.0f/NPT));
        sincosf(ad, &ds[k], &dc[k]);
    }
    for (int j=0; j<32; j++){
        int n = n0 + (j<<5);
        float accv[CH];
        #pragma unroll
        for (int o=0; o<CH; o++) accv[o] = pb[o];
        #pragma unroll
        for (int k=0; k<MODES; k++){
            float c = ck[k], s = sk[k];
            #pragma unroll
            for (int o=0; o<CH; o++){
                accv[o] = fmaf( zz[(o*MODES+k)*2],     c, accv[o]);
                accv[o] = fmaf(-zz[(o*MODES+k)*2 + 1], s, accv[o]);
            }
            float nc = c*dc[k] - s*ds[k];
            sk[k] = fmaf(c, ds[k], s*dc[k]);
            ck[k] = nc;
        }
        #pragma unroll
        for (int o=0; o<CH; o++)
            out[((size_t)(b*CH + o))*NPT + n] = accv[o];
    }
}

// ---------------- launch ----------------
extern "C" void kernel_launch(void* const* d_in, const int* in_sizes, int n_in,
                              void* d_out, int out_size)
{
    const float* u0     = (const float*)d_in[0];
    const float* t_span = (const float*)d_in[1];
    const float* conv_w = (const float*)d_in[2];
    const float* conv_b = (const float*)d_in[3];
    const float* sw_r   = (const float*)d_in[4];
    const float* sw_i   = (const float*)d_in[5];
    const float* proj_w = (const float*)d_in[6];
    const float* proj_b = (const float*)d_in[7];
    float* out = (float*)d_out;

    float* bufA = nullptr;
    cudaGetSymbolAddress((void**)&bufA, g_bufA);

    const int rk_smem = (CH*SROW + 4*CH*EDG + TSTEPS + CH*CH*3 + CH + CH*8) * sizeof(float);
    cudaFuncSetAttribute(rk4_fused, cudaFuncAttributeMaxDynamicSharedMemorySize, rk_smem);

    dim3 rkgrid(NBLK, BB);
    rk4_fused<<<rkgrid, RKTHREADS, rk_smem>>>(u0, bufA, t_span, conv_w, conv_b);

    fwd_dft_kernel<<<BB*CH*FBLK, 256>>>(bufA);
    synth_kernel<<<BB*8, 256>>>(out, sw_r, sw_i, proj_w, proj_b);
}

// round 17
// speedup vs baseline: 1.1525x; 1.0374x over previous
#include <cuda_runtime.h>

#define CH 6
#define MODES 16
#define BB 32
#define NPT 65536
#define NMASK 65535
#define TSTEPS 8

#define EXT 1026                 // logical window: indices 0..1025
#define SROW 1032                // padded row stride (float4 alignment)
#define VMARG 29                 // validity margin after 28 stage-shrinks (+1 end)
#define CORE 968                 // EXT - 2*VMARG, valid output core [29, 997)
#define NBLK 68                  // 68*968 = 65824 >= NPT
#define RKTHREADS 256            // 4 points/thread tile [1,1025) exactly
#define EDG 260                  // per-channel stride in edge arrays
#define FBLK 8                   // blocks per (b,i) in forward DFT

// -------- scratch (no allocations allowed) --------
__device__ float g_bufA[BB*CH*NPT];
__device__ float g_part[BB*CH*FBLK*MODES*2];

__device__ __forceinline__ float htanh(float x){
    float y;
    asm("tanh.approx.f32 %0, %1;" : "=f"(y) : "f"(x));
    return y;
}

// ---------------- stage ----------------
// 4 points/thread: own p0+1..p0+4 (p0=4*tid), window [p0, p0+5]; threads tile
// [1,1025) exactly — NO tail. Linearity split: cu = conv(u)+bias (stage 0);
// stages 1-3: a = cu + cc*conv(k). Weights/bias in SMEM (broadcast LDS).
// Edge arrays (double-buffered, stride-1): eL[i]=k(4i) (i=0 sentinel),
// eR[i]=k(4i+1) (i=256 sentinel). Stages 1-3 read ONLY edges/kr (not su).

template<int S>
__device__ __forceinline__ void stage(
    float (&cu)[CH][4],
    const float* __restrict__ eLr, const float* __restrict__ eRr,
    float* __restrict__ eLw, float* __restrict__ eRw,
    const float* __restrict__ su,
    const float* __restrict__ sw, const float* __restrict__ sb,
    float cc, float aw, int gofs, int tid, bool edge,
    float (&kr)[CH][4], float (&acc)[CH][4])
{
    const int p0 = 4*tid;
    float a[CH][4];
    #pragma unroll
    for (int co=0; co<CH; co++){ a[co][0]=0.f; a[co][1]=0.f; a[co][2]=0.f; a[co][3]=0.f; }

    if (S == 0){
        #pragma unroll
        for (int ci=0; ci<CH; ci++){
            const float* ru = su + ci*SROW + p0;
            float4 u0 = *(const float4*)ru;          // p0..p0+3 (aligned)
            float2 u1 = *(const float2*)(ru + 4);    // p0+4, p0+5
            float xv[6] = {u0.x, u0.y, u0.z, u0.w, u1.x, u1.y};
            #pragma unroll
            for (int co=0; co<CH; co++){
                const float w0 = sw[(co*CH+ci)*3 + 0];
                const float w1 = sw[(co*CH+ci)*3 + 1];
                const float w2 = sw[(co*CH+ci)*3 + 2];
                #pragma unroll
                for (int j=0; j<4; j++)
                    a[co][j] = fmaf(w0, xv[j], fmaf(w1, xv[j+1], fmaf(w2, xv[j+2], a[co][j])));
            }
        }
        // fold bias into cu
        #pragma unroll
        for (int co=0; co<CH; co++){
            const float bias = sb[co];
            #pragma unroll
            for (int j=0; j<4; j++){
                a[co][j] += bias;
                cu[co][j] = a[co][j];
            }
        }
    } else {
        // hoisted, batched edge loads (MLP)
        float xl[CH], xr[CH];
        #pragma unroll
        for (int ci=0; ci<CH; ci++){
            xl[ci] = eLr[ci*EDG + tid];
            xr[ci] = eRr[ci*EDG + tid + 1];
        }
        #pragma unroll
        for (int ci=0; ci<CH; ci++){
            float xvk[6];
            xvk[0] = xl[ci];
            xvk[1] = kr[ci][0]; xvk[2] = kr[ci][1];
            xvk[3] = kr[ci][2]; xvk[4] = kr[ci][3];
            xvk[5] = xr[ci];
            if (edge){
                #pragma unroll
                for (int j=0; j<6; j++)
                    if ((unsigned)(gofs + p0 + j) >= NPT) xvk[j] = 0.f;
            }
            #pragma unroll
            for (int co=0; co<CH; co++){
                const float w0 = sw[(co*CH+ci)*3 + 0];
                const float w1 = sw[(co*CH+ci)*3 + 1];
                const float w2 = sw[(co*CH+ci)*3 + 2];
                #pragma unroll
                for (int j=0; j<4; j++)
                    a[co][j] = fmaf(w0, xvk[j], fmaf(w1, xvk[j+1], fmaf(w2, xvk[j+2], a[co][j])));
            }
        }
        #pragma unroll
        for (int co=0; co<CH; co++)
            #pragma unroll
            for (int j=0; j<4; j++) a[co][j] = fmaf(cc, a[co][j], cu[co][j]);
    }

    #pragma unroll
    for (int co=0; co<CH; co++){
        #pragma unroll
        for (int j=0; j<4; j++){
            float t = htanh(a[co][j]);
            kr[co][j] = t;
            acc[co][j] = fmaf(aw, t, acc[co][j]);
        }
        if (S < 3){
            eLw[co*EDG + tid + 1] = kr[co][3];   // k(4t+4)
            eRw[co*EDG + tid]     = kr[co][0];   // k(4t+1)
        }
    }
    if (S < 3) __syncthreads();
}

// ---------------- fused 7-step RK4 kernel ----------------
__global__ void __launch_bounds__(RKTHREADS, 2)
rk4_fused(const float* __restrict__ src, float* __restrict__ dst,
          const float* __restrict__ t_span,
          const float* __restrict__ conv_w, const float* __restrict__ conv_b)
{
    extern __shared__ float sm[];
    float* s_su   = sm;                      // CH*SROW
    float* s_eL   = s_su + CH*SROW;          // 2*CH*EDG
    float* s_eR   = s_eL + 2*CH*EDG;         // 2*CH*EDG
    float* s_ts   = s_eR + 2*CH*EDG;         // TSTEPS
    float* s_w    = s_ts + TSTEPS;           // CH*CH*3 = 108
    float* s_b    = s_w + CH*CH*3;           // CH
    float* s_hand = s_b + CH;                // CH*8 warp-boundary acc handoff

    const int b    = blockIdx.y;
    const int bx   = blockIdx.x;
    const int gofs = bx*CORE - VMARG;
    const int tid  = threadIdx.x;
    const bool edge = (bx == 0) | (bx == gridDim.x - 1);
    const int p0   = 4*tid;
    const int lane = tid & 31;
    const int wid  = tid >> 5;

    if (tid < CH){
        s_eL[tid*EDG + 0] = 0.f;           // k(0) sentinels, both buffers
        s_eL[(CH+tid)*EDG + 0] = 0.f;
        s_eR[tid*EDG + 256] = 0.f;         // k(1025) sentinels, both buffers
        s_eR[(CH+tid)*EDG + 256] = 0.f;
        s_b[tid] = conv_b[tid];
    }
    if (tid < TSTEPS)  s_ts[tid] = t_span[tid];
    if (tid < CH*CH*3) s_w[tid]  = conv_w[tid];
    #pragma unroll
    for (int ch=0; ch<CH; ch++){
        const float* sc = src + ((size_t)b*CH + ch)*NPT;
        for (int p=tid; p<EXT; p+=RKTHREADS){
            int g = gofs + p;
            s_su[ch*SROW + p] = ((unsigned)g < NPT) ? sc[g] : 0.f;
        }
    }
    __syncthreads();

    float* eL0 = s_eL;  float* eL1 = s_eL + CH*EDG;
    float* eR0 = s_eR;  float* eR1 = s_eR + CH*EDG;

    #pragma unroll 1
    for (int s=0; s<TSTEPS-1; s++){
        const float dt  = s_ts[s+1] - s_ts[s];
        const float hdt = 0.5f*dt;

        float cu[CH][4], kr[CH][4], acc[CH][4];
        #pragma unroll
        for (int co=0; co<CH; co++){
            acc[co][0]=0.f; acc[co][1]=0.f; acc[co][2]=0.f; acc[co][3]=0.f;
        }

        stage<0>(cu, eL0,eR0, eL0,eR0, s_su, s_w, s_b, 0.f, 1.f, gofs, tid, edge, kr, acc);
        stage<1>(cu, eL0,eR0, eL1,eR1, s_su, s_w, s_b, hdt, 2.f, gofs, tid, edge, kr, acc);
        stage<2>(cu, eL1,eR1, eL0,eR0, s_su, s_w, s_b, hdt, 2.f, gofs, tid, edge, kr, acc);
        stage<3>(cu, eL0,eR0, eL1,eR1, s_su, s_w, s_b, dt,  1.f, gofs, tid, edge, kr, acc);

        // warp-boundary handoff: warp w lane 31 publishes acc[3] (point 128w+128)
        if (lane == 31){
            #pragma unroll
            for (int co=0; co<CH; co++) s_hand[co*8 + wid] = acc[co][3];
        }
        __syncthreads();

        // conflict-free epilogue: thread t RMWs aligned quad [4t, 4t+4).
        // Point 4t's acc comes from neighbor t-1 (shfl_up / handoff array).
        // Points 0 (garbage-but-finite) and 1024,1025 (stale) are inside the
        // 29-point discard margin. Edge blocks select 0 for OOB components.
        const float dt6 = dt * (1.0f/6.0f);
        #pragma unroll
        for (int co=0; co<CH; co++){
            float ap = __shfl_up_sync(0xffffffffu, acc[co][3], 1);
            if (lane == 0 && wid > 0) ap = s_hand[co*8 + wid - 1];
            float* rp = s_su + co*SROW + p0;
            float4 v = *(const float4*)rp;
            float n0 = fmaf(dt6, ap,         v.x);
            float n1 = fmaf(dt6, acc[co][0], v.y);
            float n2 = fmaf(dt6, acc[co][1], v.z);
            float n3 = fmaf(dt6, acc[co][2], v.w);
            if (edge){
                n0 = ((unsigned)(gofs + p0 + 0) < NPT) ? n0 : 0.f;
                n1 = ((unsigned)(gofs + p0 + 1) < NPT) ? n1 : 0.f;
                n2 = ((unsigned)(gofs + p0 + 2) < NPT) ? n2 : 0.f;
                n3 = ((unsigned)(gofs + p0 + 3) < NPT) ? n3 : 0.f;
            }
            *(float4*)rp = make_float4(n0, n1, n2, n3);
        }
        __syncthreads();            // updated su visible to next step's stage 0
    }

    // final store: valid core [29, 997)
    #pragma unroll
    for (int co=0; co<CH; co++){
        float* dp = dst + ((size_t)b*CH + co)*NPT;
        const float* rp = s_su + co*SROW;
        #pragma unroll
        for (int j=0; j<4; j++){
            int p = p0 + 1 + j;
            int g = gofs + p;
            if (p >= VMARG && p < EXT-VMARG && (unsigned)g < NPT)
                dp[g] = rp[p];
        }
    }
}

// ---------------- forward 16-mode DFT: factored (no per-point rotation) ----------------
// Thread owns base = seg*256 + tid, points n = base + 2048*j (j<32), coalesced.
// e^{-i 2pi k n/N} = cb_k(base) * T[k][j],  T[k][j] = e^{-i 2pi k j / 32} (smem table).
// A_k = sum_j x_j * T[k][j]  (2 FMA per mode per point);  X_k = cb_k * A_k.
__global__ void __launch_bounds__(256)
fwd_dft_kernel(const float* __restrict__ u)
{
    const int blk  = blockIdx.x;                 // [0, BB*CH*FBLK)
    const int seg  = blk & (FBLK-1);
    const int bi   = blk / FBLK;                 // b*CH + i
    const int tid  = threadIdx.x;
    const int lane = tid & 31, warp = tid >> 5;
    const int base = seg*256 + tid;
    const float* x = u + (size_t)bi*NPT + base;

    __shared__ float2 sT[MODES*32];              // T[k][j]
    {
        // 512 entries, 256 threads: 2 each
        #pragma unroll
        for (int e = tid; e < MODES*32; e += 256){
            int k = e >> 5, j = e & 31;
            float ang = -6.283185307179586f * (float)((k*j) & 31) * (1.0f/32.0f);
            float s, c; sincosf(ang, &s, &c);
            sT[e] = make_float2(c, s);
        }
    }
    __syncthreads();

    const float TWO_PI = 6.283185307179586f;
    float cbr[MODES], cbi[MODES];
    #pragma unroll
    for (int k=0; k<MODES; k++){
        float ang = -TWO_PI * ((float)((k*base) & NMASK) * (1.0f/NPT));
        sincosf(ang, &cbi[k], &cbr[k]);          // cbi=sin(-θ), cbr=cos
    }

    float Ar[MODES], Ai[MODES];
    #pragma unroll
    for (int k=0; k<MODES; k++){ Ar[k]=0.f; Ai[k]=0.f; }

    #pragma unroll 1
    for (int jb=0; jb<4; jb++){
        float xv[8];
        #pragma unroll
        for (int q=0; q<8; q++)
            xv[q] = __ldg(x + ((jb*8 + q) << 11));   // stride 2048
        #pragma unroll
        for (int q=0; q<8; q++){
            const int j = jb*8 + q;
            const float v = xv[q];
            #pragma unroll
            for (int k=0; k<MODES; k++){
                float2 t = sT[k*32 + j];             // broadcast LDS.64
                Ar[k] = fmaf(v, t.x, Ar[k]);
                Ai[k] = fmaf(v, t.y, Ai[k]);
            }
        }
    }

    // X_k = cb_k * A_k, then butterfly-reduce across warp
    float cr[MODES], cim[MODES];
    #pragma unroll
    for (int k=0; k<MODES; k++){
        cr[k]  = cbr[k]*Ar[k] - cbi[k]*Ai[k];
        cim[k] = cbr[k]*Ai[k] + cbi[k]*Ar[k];
    }
    #pragma unroll
    for (int k=0; k<MODES; k++){
        #pragma unroll
        for (int off=16; off; off>>=1){
            cr[k]  += __shfl_xor_sync(0xffffffffu, cr[k],  off);
            cim[k] += __shfl_xor_sync(0xffffffffu, cim[k], off);
        }
    }
    __shared__ float red[8][MODES*2];
    if (lane == 0){
        #pragma unroll
        for (int k=0; k<MODES; k++){
            red[warp][2*k]   = cr[k];
            red[warp][2*k+1] = cim[k];
        }
    }
    __syncthreads();
    if (tid < MODES*2){
        float s = 0.f;
        #pragma unroll
        for (int w=0; w<8; w++) s += red[w][tid];
        g_part[(bi*FBLK + seg)*(MODES*2) + tid] = s;
    }
}

// ---------------- synthesis: fused mix + 16-mode irfft + bias (R11 proven) ----------------
__global__ void __launch_bounds__(256)
synth_kernel(float* __restrict__ out,
             const float* __restrict__ sw_r, const float* __restrict__ sw_i,
             const float* __restrict__ proj_w, const float* __restrict__ proj_b)
{
    const int blk  = blockIdx.x;        // b*8 + seg
    const int b    = blk >> 3, seg = blk & 7;
    const int tid  = threadIdx.x, lane = tid & 31, warp = tid >> 5;
    const int n0   = seg*8192 + warp*1024 + lane;

    __shared__ float zz[CH*MODES*2];
    __shared__ float pb[CH];
    if (tid < CH*MODES){
        const int o = tid / MODES, k = tid % MODES;
        float Zr = 0.f, Zi = 0.f;
        #pragma unroll
        for (int i=0; i<CH; i++){
            float Xr=0.f, Xi=0.f;
            int bi = b*CH + i;
            #pragma unroll
            for (int s=0; s<FBLK; s++){
                Xr += g_part[(bi*FBLK+s)*(MODES*2) + 2*k];
                Xi += g_part[(bi*FBLK+s)*(MODES*2) + 2*k + 1];
            }
            float Wr=0.f, Wi=0.f;
            #pragma unroll
            for (int c=0; c<CH; c++){
                float pw = proj_w[o*CH + c];
                Wr = fmaf(sw_r[(i*CH+c)*MODES + k], pw, Wr);
                Wi = fmaf(sw_i[(i*CH+c)*MODES + k], pw, Wi);
            }
            Zr += Xr*Wr - Xi*Wi;
            Zi += Xr*Wi + Xi*Wr;
        }
        float scale = (k==0) ? (1.0f/NPT) : (2.0f/NPT);   // irfft: DC once, others doubled
        zz[(o*MODES+k)*2]     = Zr*scale;
        zz[(o*MODES+k)*2 + 1] = Zi*scale;
    }
    if (tid < CH) pb[tid] = proj_b[tid];
    __syncthreads();

    const float TWO_PI = 6.283185307179586f;
    float ck[MODES], sk[MODES], dc[MODES], ds[MODES];
    #pragma unroll
    for (int k=0; k<MODES; k++){
        float a0 = TWO_PI * ((float)((k*n0) & NMASK) * (1.0f/NPT));
        sincosf(a0, &sk[k], &ck[k]);
        float ad = TWO_PI * ((float)(k*32) * (1.0f/NPT));
        sincosf(ad, &ds[k], &dc[k]);
    }
    for (int j=0; j<32; j++){
        int n = n0 + (j<<5);
        float accv[CH];
        #pragma unroll
        for (int o=0; o<CH; o++) accv[o] = pb[o];
        #pragma unroll
        for (int k=0; k<MODES; k++){
            float c = ck[k], s = sk[k];
            #pragma unroll
            for (int o=0; o<CH; o++){
                accv[o] = fmaf( zz[(o*MODES+k)*2],     c, accv[o]);
                accv[o] = fmaf(-zz[(o*MODES+k)*2 + 1], s, accv[o]);
            }
            float nc = c*dc[k] - s*ds[k];
            sk[k] = fmaf(c, ds[k], s*dc[k]);
            ck[k] = nc;
        }
        #pragma unroll
        for (int o=0; o<CH; o++)
            out[((size_t)(b*CH + o))*NPT + n] = accv[o];
    }
}

// ---------------- launch ----------------
extern "C" void kernel_launch(void* const* d_in, const int* in_sizes, int n_in,
                              void* d_out, int out_size)
{
    const float* u0     = (const float*)d_in[0];
    const float* t_span = (const float*)d_in[1];
    const float* conv_w = (const float*)d_in[2];
    const float* conv_b = (const float*)d_in[3];
    const float* sw_r   = (const float*)d_in[4];
    const float* sw_i   = (const float*)d_in[5];
    const float* proj_w = (const float*)d_in[6];
    const float* proj_b = (const float*)d_in[7];
    float* out = (float*)d_out;

    float* bufA = nullptr;
    cudaGetSymbolAddress((void**)&bufA, g_bufA);

    const int rk_smem = (CH*SROW + 4*CH*EDG + TSTEPS + CH*CH*3 + CH + CH*8) * sizeof(float);
    cudaFuncSetAttribute(rk4_fused, cudaFuncAttributeMaxDynamicSharedMemorySize, rk_smem);

    dim3 rkgrid(NBLK, BB);
    rk4_fused<<<rkgrid, RKTHREADS, rk_smem>>>(u0, bufA, t_span, conv_w, conv_b);

    fwd_dft_kernel<<<BB*CH*FBLK, 256>>>(bufA);
    synth_kernel<<<BB*8, 256>>>(out, sw_r, sw_i, proj_w, proj_b);
}